// round 1
// baseline (speedup 1.0000x reference)
#include <cuda_runtime.h>
#include <math.h>

#define B_ 2
#define N_ 2048
#define C_ 256
#define L_ 4
#define H_ 8
#define DH_ 32
#define ROWS_ (B_ * N_)          // 4096
#define QKV_N_ (3 * C_)          // 768

// ---------------- scratch (device globals; no allocs allowed) ----------------
__device__ float g_x   [ROWS_ * C_];      // current activations
__device__ float g_qkv [ROWS_ * QKV_N_]; // qkv projection
__device__ float g_attn[ROWS_ * C_];      // attention output
__device__ float g_tmp [ROWS_ * C_];      // proj-out / mlp-out
__device__ float g_h   [ROWS_ * C_];      // mlp hidden

// ---------------- positional embedding add ----------------
__global__ void addpos_kernel(const float* __restrict__ x, float* __restrict__ out) {
    int n = blockIdx.x;           // 0..2047
    int c = threadIdx.x;          // 0..255
    int j = c & ~1;               // even index (2i)
    float div = __expf((float)j * (-9.210340371976184f / 256.0f));
    float ang = (float)n * div;
    float pe = (c & 1) ? cosf(ang) : sinf(ang);
    size_t i0 = (size_t)n * C_ + c;
    size_t i1 = (size_t)(N_ + n) * C_ + c;
    out[i0] = x[i0] + pe;
    out[i1] = x[i1] + pe;
}

// ---------------- tiled SGEMM: C = A(MxK) @ B(KxN) [+bias][+gelu] ----------------
// mode: 0=none, 1=bias, 2=bias+gelu(exact)
#define BM 64
#define BN 64
#define BK 16

__global__ __launch_bounds__(256) void sgemm_kernel(
    const float* __restrict__ A, const float* __restrict__ B,
    const float* __restrict__ bias, float* __restrict__ C,
    int M, int N, int K, int mode)
{
    __shared__ float As[BK][BM];
    __shared__ float Bs[BK][BN];

    int tid = threadIdx.x;
    int tx = tid & 15;            // 0..15
    int ty = tid >> 4;            // 0..15
    int brow = blockIdx.y * BM;
    int bcol = blockIdx.x * BN;

    float acc[4][4];
#pragma unroll
    for (int i = 0; i < 4; i++)
#pragma unroll
        for (int j = 0; j < 4; j++) acc[i][j] = 0.f;

    int arow = tid >> 2;          // 0..63
    int acol = (tid & 3) << 2;    // 0,4,8,12
    int brow_l = tid >> 4;        // 0..15
    int bcol_l = (tid & 15) << 2; // 0..60

    for (int k0 = 0; k0 < K; k0 += BK) {
        float4 av = *(const float4*)(A + (size_t)(brow + arow) * K + k0 + acol);
        As[acol + 0][arow] = av.x;
        As[acol + 1][arow] = av.y;
        As[acol + 2][arow] = av.z;
        As[acol + 3][arow] = av.w;
        float4 bv = *(const float4*)(B + (size_t)(k0 + brow_l) * N + bcol + bcol_l);
        *(float4*)(&Bs[brow_l][bcol_l]) = bv;
        __syncthreads();
#pragma unroll
        for (int k = 0; k < BK; k++) {
            float4 a = *(const float4*)(&As[k][ty << 2]);
            float4 b = *(const float4*)(&Bs[k][tx << 2]);
            float ar[4] = {a.x, a.y, a.z, a.w};
            float br[4] = {b.x, b.y, b.z, b.w};
#pragma unroll
            for (int i = 0; i < 4; i++)
#pragma unroll
                for (int j = 0; j < 4; j++) acc[i][j] += ar[i] * br[j];
        }
        __syncthreads();
    }

#pragma unroll
    for (int i = 0; i < 4; i++) {
        int row = brow + (ty << 2) + i;
#pragma unroll
        for (int j = 0; j < 4; j++) {
            int col = bcol + (tx << 2) + j;
            float v = acc[i][j];
            if (mode >= 1) v += bias[col];
            if (mode == 2) v = 0.5f * v * (1.0f + erff(v * 0.70710678118654752f));
            C[(size_t)row * N + col] = v;
        }
    }
}

// ---------------- flash attention (fp32, streaming softmax) ----------------
// grid: (N/128, H, B), 128 threads; thread t owns query qt*128+t
__global__ __launch_bounds__(128) void attn_kernel(
    const float* __restrict__ qkv, float* __restrict__ out)
{
    int qt = blockIdx.x, h = blockIdx.y, b = blockIdx.z;
    int tid = threadIdx.x;
    int warp = tid >> 5, lane = tid & 31;
    int q = qt * 128 + tid;

    __shared__ float sk[128][DH_];
    __shared__ float sv[128][DH_];

    const float scale = 0.17677669529663687f; // 1/sqrt(32)
    float qreg[DH_], o[DH_];
    const float* qptr = qkv + ((size_t)(b * N_ + q) * QKV_N_) + h * DH_;
#pragma unroll
    for (int d = 0; d < DH_; d++) { qreg[d] = qptr[d] * scale; o[d] = 0.f; }

    float m = -1e30f, lsum = 0.f;

    for (int kt = 0; kt < N_ / 128; kt++) {
        const float* kbase = qkv + ((size_t)(b * N_ + kt * 128) * QKV_N_) + C_ + h * DH_;
        const float* vbase = kbase + C_;
        // warp-coalesced tile load: lane = channel, rows strided by warp
#pragma unroll 4
        for (int it = 0; it < 32; it++) {
            int r = warp * 32 + it;
            sk[r][lane] = kbase[(size_t)r * QKV_N_ + lane];
            sv[r][lane] = vbase[(size_t)r * QKV_N_ + lane];
        }
        __syncthreads();

        for (int j = 0; j < 128; j++) {
            float s = 0.f;
#pragma unroll
            for (int d = 0; d < DH_; d++) s += qreg[d] * sk[j][d];
            if (s > m) {
                float c = __expf(m - s);
                lsum *= c;
#pragma unroll
                for (int d = 0; d < DH_; d++) o[d] *= c;
                m = s;
            }
            float p = __expf(s - m);
            lsum += p;
#pragma unroll
            for (int d = 0; d < DH_; d++) o[d] += p * sv[j][d];
        }
        __syncthreads();
    }

    float inv = 1.0f / lsum;
    float* optr = out + ((size_t)(b * N_ + q) * C_) + h * DH_;
#pragma unroll
    for (int d = 0; d < DH_; d++) optr[d] = o[d] * inv;
}

// ---------------- fused residual add + layernorm ----------------
__global__ __launch_bounds__(256) void add_ln_kernel(
    const float* __restrict__ x, const float* __restrict__ y,
    const float* __restrict__ g, const float* __restrict__ be,
    float* __restrict__ out)
{
    int row = blockIdx.x;
    int c = threadIdx.x;
    float v = x[(size_t)row * C_ + c] + y[(size_t)row * C_ + c];

    __shared__ float red[8];
    // mean
    float s = v;
#pragma unroll
    for (int o = 16; o > 0; o >>= 1) s += __shfl_down_sync(0xffffffffu, s, o);
    if ((c & 31) == 0) red[c >> 5] = s;
    __syncthreads();
    float mu = 0.f;
#pragma unroll
    for (int i = 0; i < 8; i++) mu += red[i];
    mu *= (1.0f / C_);
    __syncthreads();
    // variance
    float dv = v - mu;
    float s2 = dv * dv;
#pragma unroll
    for (int o = 16; o > 0; o >>= 1) s2 += __shfl_down_sync(0xffffffffu, s2, o);
    if ((c & 31) == 0) red[c >> 5] = s2;
    __syncthreads();
    float var = 0.f;
#pragma unroll
    for (int i = 0; i < 8; i++) var += red[i];
    var *= (1.0f / C_);

    out[(size_t)row * C_ + c] = dv * rsqrtf(var + 1e-6f) * g[c] + be[c];
}

// ---------------- launch ----------------
extern "C" void kernel_launch(void* const* d_in, const int* in_sizes, int n_in,
                              void* d_out, int out_size)
{
    const float* x_in   = (const float*)d_in[0];
    const float* qkv_w  = (const float*)d_in[1];
    const float* proj_w = (const float*)d_in[2];
    const float* proj_b = (const float*)d_in[3];
    const float* w1     = (const float*)d_in[4];
    const float* b1     = (const float*)d_in[5];
    const float* w2     = (const float*)d_in[6];
    const float* b2     = (const float*)d_in[7];
    const float* g1     = (const float*)d_in[8];
    const float* be1    = (const float*)d_in[9];
    const float* g2     = (const float*)d_in[10];
    const float* be2    = (const float*)d_in[11];
    float* out = (float*)d_out;

    float *px, *pqkv, *pattn, *ptmp, *ph;
    cudaGetSymbolAddress((void**)&px,   g_x);
    cudaGetSymbolAddress((void**)&pqkv, g_qkv);
    cudaGetSymbolAddress((void**)&pattn,g_attn);
    cudaGetSymbolAddress((void**)&ptmp, g_tmp);
    cudaGetSymbolAddress((void**)&ph,   g_h);

    addpos_kernel<<<N_, C_>>>(x_in, px);

    for (int l = 0; l < L_; l++) {
        // qkv = x @ qkv_w[l]
        sgemm_kernel<<<dim3(QKV_N_ / BN, ROWS_ / BM), 256>>>(
            px, qkv_w + (size_t)l * C_ * QKV_N_, nullptr, pqkv,
            ROWS_, QKV_N_, C_, 0);
        // attention
        attn_kernel<<<dim3(N_ / 128, H_, B_), 128>>>(pqkv, pattn);
        // proj
        sgemm_kernel<<<dim3(C_ / BN, ROWS_ / BM), 256>>>(
            pattn, proj_w + (size_t)l * C_ * C_, proj_b + (size_t)l * C_, ptmp,
            ROWS_, C_, C_, 1);
        // x = LN(x + proj_out)
        add_ln_kernel<<<ROWS_, C_>>>(px, ptmp, g1 + (size_t)l * C_, be1 + (size_t)l * C_, px);
        // h = gelu(x @ w1 + b1)
        sgemm_kernel<<<dim3(C_ / BN, ROWS_ / BM), 256>>>(
            px, w1 + (size_t)l * C_ * C_, b1 + (size_t)l * C_, ph,
            ROWS_, C_, C_, 2);
        // mlp = h @ w2 + b2
        sgemm_kernel<<<dim3(C_ / BN, ROWS_ / BM), 256>>>(
            ph, w2 + (size_t)l * C_ * C_, b2 + (size_t)l * C_, ptmp,
            ROWS_, C_, C_, 1);
        // x = LN(x + mlp) ; final layer writes straight to d_out
        float* dst = (l == L_ - 1) ? out : px;
        add_ln_kernel<<<ROWS_, C_>>>(px, ptmp, g2 + (size_t)l * C_, be2 + (size_t)l * C_, dst);
    }
}

// round 3
// speedup vs baseline: 2.4323x; 2.4323x over previous
#include <cuda_runtime.h>
#include <math.h>
#include <stdint.h>

#define B_ 2
#define N_ 2048
#define C_ 256
#define L_ 4
#define H_ 8
#define DH_ 32
#define ROWS_ (B_ * N_)          // 4096
#define QKV_N_ (3 * C_)          // 768
#define LOG2E_ 1.4426950408889634f
#define QSCALE_ (0.17677669529663687f * LOG2E_)   // 1/sqrt(32) * log2(e)

// ===================== scratch (device globals; no allocs allowed) =====================
__device__ float g_x   [ROWS_ * C_];
__device__ float g_qkv [ROWS_ * QKV_N_];
__device__ float g_attn[ROWS_ * C_];
__device__ float g_tmp [ROWS_ * C_];
__device__ float g_h   [ROWS_ * C_];
// transposed weights: [N][K] K-major
__device__ float g_qkvT [L_ * QKV_N_ * C_];
__device__ float g_projT[L_ * C_ * C_];
__device__ float g_w1T  [L_ * C_ * C_];
__device__ float g_w2T  [L_ * C_ * C_];

// ===================== mma.sync tf32 helpers (baseline PTX, sm_80+) =====================
__device__ __forceinline__ uint32_t f2tf(float f) {
    uint32_t u;
    asm("cvt.rna.tf32.f32 %0, %1;" : "=r"(u) : "f"(f));
    return u;
}

// D(16x8) += A(16x8) @ B(8x8), row.col, tf32 in / f32 accum
__device__ __forceinline__ void mma_tf32(float* d, const uint32_t* a, const uint32_t* b) {
    asm volatile(
        "mma.sync.aligned.m16n8k8.row.col.f32.tf32.tf32.f32 "
        "{%0,%1,%2,%3}, {%4,%5,%6,%7}, {%8,%9}, {%0,%1,%2,%3};"
        : "+f"(d[0]), "+f"(d[1]), "+f"(d[2]), "+f"(d[3])
        : "r"(a[0]), "r"(a[1]), "r"(a[2]), "r"(a[3]), "r"(b[0]), "r"(b[1]));
}

// ===================== weight transpose: out[n][k] = in[k][n], per layer (blockIdx.z) ====
__global__ __launch_bounds__(256) void transpose_kernel(
    const float* __restrict__ in, float* __restrict__ out, int K, int Nn)
{
    __shared__ float t[32][33];
    int z = blockIdx.z;
    const float* inl = in + (size_t)z * K * Nn;
    float* outl = out + (size_t)z * Nn * K;
    int tx = threadIdx.x, ty = threadIdx.y;
    int x = blockIdx.x * 32 + tx;     // n
    int y = blockIdx.y * 32 + ty;     // k
#pragma unroll
    for (int j = 0; j < 4; j++)
        t[ty + 8 * j][tx] = inl[(size_t)(y + 8 * j) * Nn + x];
    __syncthreads();
    int x2 = blockIdx.y * 32 + tx;    // k
    int y2 = blockIdx.x * 32 + ty;    // n
#pragma unroll
    for (int j = 0; j < 4; j++)
        outl[(size_t)(y2 + 8 * j) * K + x2] = t[tx][ty + 8 * j];
}

// ===================== positional embedding add =====================
__global__ void addpos_kernel(const float* __restrict__ x, float* __restrict__ out) {
    int n = blockIdx.x;
    int c = threadIdx.x;
    int j = c & ~1;
    float div = __expf((float)j * (-9.210340371976184f / 256.0f));
    float ang = (float)n * div;
    float pe = (c & 1) ? cosf(ang) : sinf(ang);
    size_t i0 = (size_t)n * C_ + c;
    size_t i1 = (size_t)(N_ + n) * C_ + c;
    out[i0] = x[i0] + pe;
    out[i1] = x[i1] + pe;
}

// ===================== tf32 mma GEMM: C = A(4096x256) @ BT(Nx256)^T =====================
// grid (Nn/128, 4096/128), 256 threads = 8 warps; warp tile 64x32; K = 256 fixed.
// mode: 0=none, 1=bias, 2=bias+gelu
#define GSTR 20   // smem row stride (floats), 16 + 4 pad

__global__ __launch_bounds__(256) void gemm_mma_kernel(
    const float* __restrict__ A, const float* __restrict__ BT,
    const float* __restrict__ bias, float* __restrict__ Cc,
    int Nn, int mode)
{
    __shared__ __align__(16) float sA[2][128 * GSTR];
    __shared__ __align__(16) float sB[2][128 * GSTR];

    const int tid = threadIdx.x, w = tid >> 5, lane = tid & 31;
    const int g = lane >> 2, tg = lane & 3;
    const int wm = (w & 1) * 64, wn = (w >> 1) * 32;
    const int brow = blockIdx.y * 128, bcol = blockIdx.x * 128;

    float acc[4][4][4];
#pragma unroll
    for (int mt = 0; mt < 4; mt++)
#pragma unroll
        for (int nt = 0; nt < 4; nt++)
#pragma unroll
            for (int i = 0; i < 4; i++) acc[mt][nt][i] = 0.f;

    const int srow = tid >> 1, shalf = (tid & 1) * 8;
    const float4* agp = (const float4*)(A + (size_t)(brow + srow) * 256 + shalf);
    const float4* bgp = (const float4*)(BT + (size_t)(bcol + srow) * 256 + shalf);

    // prefetch iter 0 (global cols shalf..shalf+7, advance 4 float4 per iter)
    float4 ra0 = agp[0], ra1 = agp[1];
    float4 rb0 = bgp[0], rb1 = bgp[1];

    const int sidx = srow * GSTR + shalf;
#pragma unroll 1
    for (int it = 0; it < 16; it++) {
        const int cur = it & 1;
        // store prefetched tile (cvt to tf32 bits)
        {
            uint4 u0 = make_uint4(f2tf(ra0.x), f2tf(ra0.y), f2tf(ra0.z), f2tf(ra0.w));
            uint4 u1 = make_uint4(f2tf(ra1.x), f2tf(ra1.y), f2tf(ra1.z), f2tf(ra1.w));
            *(uint4*)(&sA[cur][sidx])     = u0;
            *(uint4*)(&sA[cur][sidx + 4]) = u1;
            uint4 v0 = make_uint4(f2tf(rb0.x), f2tf(rb0.y), f2tf(rb0.z), f2tf(rb0.w));
            uint4 v1 = make_uint4(f2tf(rb1.x), f2tf(rb1.y), f2tf(rb1.z), f2tf(rb1.w));
            *(uint4*)(&sB[cur][sidx])     = v0;
            *(uint4*)(&sB[cur][sidx + 4]) = v1;
        }
        __syncthreads();
        // prefetch next tile
        if (it < 15) {
            ra0 = agp[(it + 1) * 4];     ra1 = agp[(it + 1) * 4 + 1];
            rb0 = bgp[(it + 1) * 4];     rb1 = bgp[(it + 1) * 4 + 1];
        }
        // compute on current buffer: 2 k-steps of 8
#pragma unroll
        for (int ks = 0; ks < 2; ks++) {
            uint32_t afr[4][4];
#pragma unroll
            for (int mt = 0; mt < 4; mt++) {
                int r = wm + mt * 16 + g;
                afr[mt][0] = __float_as_uint(sA[cur][(r    ) * GSTR + ks * 8 + tg]);
                afr[mt][1] = __float_as_uint(sA[cur][(r + 8) * GSTR + ks * 8 + tg]);
                afr[mt][2] = __float_as_uint(sA[cur][(r    ) * GSTR + ks * 8 + tg + 4]);
                afr[mt][3] = __float_as_uint(sA[cur][(r + 8) * GSTR + ks * 8 + tg + 4]);
            }
            uint32_t bfr[4][2];
#pragma unroll
            for (int nt = 0; nt < 4; nt++) {
                int n = wn + nt * 8 + g;
                bfr[nt][0] = __float_as_uint(sB[cur][n * GSTR + ks * 8 + tg]);
                bfr[nt][1] = __float_as_uint(sB[cur][n * GSTR + ks * 8 + tg + 4]);
            }
#pragma unroll
            for (int mt = 0; mt < 4; mt++)
#pragma unroll
                for (int nt = 0; nt < 4; nt++)
                    mma_tf32(acc[mt][nt], afr[mt], bfr[nt]);
        }
        __syncthreads();
    }

    // epilogue
#pragma unroll
    for (int mt = 0; mt < 4; mt++) {
        int r0 = brow + wm + mt * 16 + g;
#pragma unroll
        for (int nt = 0; nt < 4; nt++) {
            int cc = bcol + wn + nt * 8 + 2 * tg;
            float bi0 = 0.f, bi1 = 0.f;
            if (mode >= 1) { bi0 = bias[cc]; bi1 = bias[cc + 1]; }
            float v0 = acc[mt][nt][0] + bi0;
            float v1 = acc[mt][nt][1] + bi1;
            float v2 = acc[mt][nt][2] + bi0;
            float v3 = acc[mt][nt][3] + bi1;
            if (mode == 2) {
                v0 = 0.5f * v0 * (1.0f + erff(v0 * 0.70710678118654752f));
                v1 = 0.5f * v1 * (1.0f + erff(v1 * 0.70710678118654752f));
                v2 = 0.5f * v2 * (1.0f + erff(v2 * 0.70710678118654752f));
                v3 = 0.5f * v3 * (1.0f + erff(v3 * 0.70710678118654752f));
            }
            *(float2*)(Cc + (size_t)r0 * Nn + cc)       = make_float2(v0, v1);
            *(float2*)(Cc + (size_t)(r0 + 8) * Nn + cc) = make_float2(v2, v3);
        }
    }
}

// ===================== tf32 mma flash attention =====================
// grid (N/128, H, B), 256 threads = 8 warps; warp w owns q rows w*16..w*16+15.
// smem: sQ/sK/sV [128][36], sP [128][132]; online softmax in exp2 domain.
#define ASTR 36
#define PSTR 132
#define SQ_OFF 0
#define SK_OFF (128 * ASTR)
#define SV_OFF (2 * 128 * ASTR)
#define SP_OFF (3 * 128 * ASTR)
#define ATTN_SMEM ((3 * 128 * ASTR + 128 * PSTR) * 4)

__global__ __launch_bounds__(256) void attn_mma_kernel(
    const float* __restrict__ qkv, float* __restrict__ out)
{
    extern __shared__ __align__(16) float sm[];
    float* sQ = sm + SQ_OFF;
    float* sK = sm + SK_OFF;
    float* sV = sm + SV_OFF;
    float* sP = sm + SP_OFF;

    const int tid = threadIdx.x, w = tid >> 5, lane = tid & 31;
    const int g = lane >> 2, tg = lane & 3;
    const int qt = blockIdx.x, h = blockIdx.y, b = blockIdx.z;

    // ---- stage Q (pre-scaled into exp2 domain, tf32) ----
    {
        const int row = tid >> 1, half = (tid & 1) * 16;
        const float4* qp = (const float4*)(qkv +
            ((size_t)(b * N_ + qt * 128 + row) * QKV_N_) + h * DH_ + half);
        uint4* dst = (uint4*)(sQ + row * ASTR + half);
#pragma unroll
        for (int i = 0; i < 4; i++) {
            float4 v = qp[i];
            dst[i] = make_uint4(f2tf(v.x * QSCALE_), f2tf(v.y * QSCALE_),
                                f2tf(v.z * QSCALE_), f2tf(v.w * QSCALE_));
        }
    }

    float oacc[4][4];
#pragma unroll
    for (int nt = 0; nt < 4; nt++)
#pragma unroll
        for (int i = 0; i < 4; i++) oacc[nt][i] = 0.f;
    float m0 = -1e30f, m1 = -1e30f, l0 = 0.f, l1 = 0.f;

    const int srow = tid >> 1, shalf = (tid & 1) * 16;

    for (int kt = 0; kt < N_ / 128; kt++) {
        // ---- stage K, V tiles (tf32) ----
        {
            const float4* kp = (const float4*)(qkv +
                ((size_t)(b * N_ + kt * 128 + srow) * QKV_N_) + C_ + h * DH_ + shalf);
            const float4* vp = (const float4*)((const float*)kp + C_);
            uint4* kd = (uint4*)(sK + srow * ASTR + shalf);
            uint4* vd = (uint4*)(sV + srow * ASTR + shalf);
#pragma unroll
            for (int i = 0; i < 4; i++) {
                float4 kv = kp[i];
                kd[i] = make_uint4(f2tf(kv.x), f2tf(kv.y), f2tf(kv.z), f2tf(kv.w));
                float4 vv = vp[i];
                vd[i] = make_uint4(f2tf(vv.x), f2tf(vv.y), f2tf(vv.z), f2tf(vv.w));
            }
        }
        __syncthreads();

        // ---- S = Q @ K^T : warp tile 16 x 128, k = 32 ----
        float sacc[16][4];
#pragma unroll
        for (int nt = 0; nt < 16; nt++)
#pragma unroll
            for (int i = 0; i < 4; i++) sacc[nt][i] = 0.f;

#pragma unroll
        for (int ks = 0; ks < 4; ks++) {
            uint32_t afr[4];
            afr[0] = __float_as_uint(sQ[(w * 16 + g    ) * ASTR + ks * 8 + tg]);
            afr[1] = __float_as_uint(sQ[(w * 16 + g + 8) * ASTR + ks * 8 + tg]);
            afr[2] = __float_as_uint(sQ[(w * 16 + g    ) * ASTR + ks * 8 + tg + 4]);
            afr[3] = __float_as_uint(sQ[(w * 16 + g + 8) * ASTR + ks * 8 + tg + 4]);
#pragma unroll
            for (int nt = 0; nt < 16; nt++) {
                uint32_t bfr[2];
                bfr[0] = __float_as_uint(sK[(nt * 8 + g) * ASTR + ks * 8 + tg]);
                bfr[1] = __float_as_uint(sK[(nt * 8 + g) * ASTR + ks * 8 + tg + 4]);
                mma_tf32(sacc[nt], afr, bfr);
            }
        }

        // ---- online softmax (rows r0 = w*16+g, r1 = r0+8) ----
        float nm0 = -1e30f, nm1 = -1e30f;
#pragma unroll
        for (int nt = 0; nt < 16; nt++) {
            nm0 = fmaxf(nm0, fmaxf(sacc[nt][0], sacc[nt][1]));
            nm1 = fmaxf(nm1, fmaxf(sacc[nt][2], sacc[nt][3]));
        }
        nm0 = fmaxf(nm0, __shfl_xor_sync(0xffffffffu, nm0, 1));
        nm0 = fmaxf(nm0, __shfl_xor_sync(0xffffffffu, nm0, 2));
        nm1 = fmaxf(nm1, __shfl_xor_sync(0xffffffffu, nm1, 1));
        nm1 = fmaxf(nm1, __shfl_xor_sync(0xffffffffu, nm1, 2));
        nm0 = fmaxf(nm0, m0);
        nm1 = fmaxf(nm1, m1);
        float f0 = exp2f(m0 - nm0), f1 = exp2f(m1 - nm1);
        m0 = nm0; m1 = nm1;

        float ps0 = 0.f, ps1 = 0.f;
        uint32_t* sPr0 = (uint32_t*)(sP + (w * 16 + g    ) * PSTR + 2 * tg);
        uint32_t* sPr1 = (uint32_t*)(sP + (w * 16 + g + 8) * PSTR + 2 * tg);
#pragma unroll
        for (int nt = 0; nt < 16; nt++) {
            float p00 = exp2f(sacc[nt][0] - m0);
            float p01 = exp2f(sacc[nt][1] - m0);
            float p10 = exp2f(sacc[nt][2] - m1);
            float p11 = exp2f(sacc[nt][3] - m1);
            ps0 += p00 + p01;
            ps1 += p10 + p11;
            *(uint2*)(sPr0 + nt * 8) = make_uint2(f2tf(p00), f2tf(p01));
            *(uint2*)(sPr1 + nt * 8) = make_uint2(f2tf(p10), f2tf(p11));
        }
        ps0 += __shfl_xor_sync(0xffffffffu, ps0, 1);
        ps0 += __shfl_xor_sync(0xffffffffu, ps0, 2);
        ps1 += __shfl_xor_sync(0xffffffffu, ps1, 1);
        ps1 += __shfl_xor_sync(0xffffffffu, ps1, 2);
        l0 = l0 * f0 + ps0;
        l1 = l1 * f1 + ps1;

        // rescale O
#pragma unroll
        for (int nt = 0; nt < 4; nt++) {
            oacc[nt][0] *= f0; oacc[nt][1] *= f0;
            oacc[nt][2] *= f1; oacc[nt][3] *= f1;
        }
        __syncwarp();

        // ---- O += P @ V : warp tile 16 x 32, k = 128 ----
#pragma unroll
        for (int ks = 0; ks < 16; ks++) {
            uint32_t afr[4];
            afr[0] = __float_as_uint(sP[(w * 16 + g    ) * PSTR + ks * 8 + tg]);
            afr[1] = __float_as_uint(sP[(w * 16 + g + 8) * PSTR + ks * 8 + tg]);
            afr[2] = __float_as_uint(sP[(w * 16 + g    ) * PSTR + ks * 8 + tg + 4]);
            afr[3] = __float_as_uint(sP[(w * 16 + g + 8) * PSTR + ks * 8 + tg + 4]);
#pragma unroll
            for (int nt = 0; nt < 4; nt++) {
                uint32_t bfr[2];
                bfr[0] = __float_as_uint(sV[(ks * 8 + tg    ) * ASTR + nt * 8 + g]);
                bfr[1] = __float_as_uint(sV[(ks * 8 + tg + 4) * ASTR + nt * 8 + g]);
                mma_tf32(oacc[nt], afr, bfr);
            }
        }
        __syncthreads();
    }

    // ---- epilogue ----
    float inv0 = 1.0f / l0, inv1 = 1.0f / l1;
    int q0 = qt * 128 + w * 16 + g;
    float* op0 = out + ((size_t)(b * N_ + q0)) * C_ + h * DH_;
    float* op1 = op0 + (size_t)8 * C_;
#pragma unroll
    for (int nt = 0; nt < 4; nt++) {
        int cc = nt * 8 + 2 * tg;
        *(float2*)(op0 + cc) = make_float2(oacc[nt][0] * inv0, oacc[nt][1] * inv0);
        *(float2*)(op1 + cc) = make_float2(oacc[nt][2] * inv1, oacc[nt][3] * inv1);
    }
}

// ===================== fused residual add + layernorm =====================
__global__ __launch_bounds__(256) void add_ln_kernel(
    const float* __restrict__ x, const float* __restrict__ y,
    const float* __restrict__ g, const float* __restrict__ be,
    float* __restrict__ out)
{
    int row = blockIdx.x;
    int c = threadIdx.x;
    float v = x[(size_t)row * C_ + c] + y[(size_t)row * C_ + c];

    __shared__ float red[8];
    float s = v;
#pragma unroll
    for (int o = 16; o > 0; o >>= 1) s += __shfl_down_sync(0xffffffffu, s, o);
    if ((c & 31) == 0) red[c >> 5] = s;
    __syncthreads();
    float mu = 0.f;
#pragma unroll
    for (int i = 0; i < 8; i++) mu += red[i];
    mu *= (1.0f / C_);
    __syncthreads();
    float dv = v - mu;
    float s2 = dv * dv;
#pragma unroll
    for (int o = 16; o > 0; o >>= 1) s2 += __shfl_down_sync(0xffffffffu, s2, o);
    if ((c & 31) == 0) red[c >> 5] = s2;
    __syncthreads();
    float var = 0.f;
#pragma unroll
    for (int i = 0; i < 8; i++) var += red[i];
    var *= (1.0f / C_);

    out[(size_t)row * C_ + c] = dv * rsqrtf(var + 1e-6f) * g[c] + be[c];
}

// ===================== launch =====================
extern "C" void kernel_launch(void* const* d_in, const int* in_sizes, int n_in,
                              void* d_out, int out_size)
{
    const float* x_in   = (const float*)d_in[0];
    const float* qkv_w  = (const float*)d_in[1];
    const float* proj_w = (const float*)d_in[2];
    const float* proj_b = (const float*)d_in[3];
    const float* w1     = (const float*)d_in[4];
    const float* b1     = (const float*)d_in[5];
    const float* w2     = (const float*)d_in[6];
    const float* b2     = (const float*)d_in[7];
    const float* g1     = (const float*)d_in[8];
    const float* be1    = (const float*)d_in[9];
    const float* g2     = (const float*)d_in[10];
    const float* be2    = (const float*)d_in[11];
    float* out = (float*)d_out;

    float *px, *pqkv, *pattn, *ptmp, *ph;
    float *pqkvT, *pprojT, *pw1T, *pw2T;
    cudaGetSymbolAddress((void**)&px,    g_x);
    cudaGetSymbolAddress((void**)&pqkv,  g_qkv);
    cudaGetSymbolAddress((void**)&pattn, g_attn);
    cudaGetSymbolAddress((void**)&ptmp,  g_tmp);
    cudaGetSymbolAddress((void**)&ph,    g_h);
    cudaGetSymbolAddress((void**)&pqkvT, g_qkvT);
    cudaGetSymbolAddress((void**)&pprojT,g_projT);
    cudaGetSymbolAddress((void**)&pw1T,  g_w1T);
    cudaGetSymbolAddress((void**)&pw2T,  g_w2T);

    static bool attr_done = false;
    if (!attr_done) {
        cudaFuncSetAttribute(attn_mma_kernel,
                             cudaFuncAttributeMaxDynamicSharedMemorySize, ATTN_SMEM);
        attr_done = true;
    }

    // transpose weights to [N][K] K-major
    transpose_kernel<<<dim3(QKV_N_ / 32, C_ / 32, L_), dim3(32, 8)>>>(qkv_w, pqkvT, C_, QKV_N_);
    transpose_kernel<<<dim3(C_ / 32, C_ / 32, L_),     dim3(32, 8)>>>(proj_w, pprojT, C_, C_);
    transpose_kernel<<<dim3(C_ / 32, C_ / 32, L_),     dim3(32, 8)>>>(w1, pw1T, C_, C_);
    transpose_kernel<<<dim3(C_ / 32, C_ / 32, L_),     dim3(32, 8)>>>(w2, pw2T, C_, C_);

    addpos_kernel<<<N_, C_>>>(x_in, px);

    for (int l = 0; l < L_; l++) {
        // qkv = x @ qkv_w[l]
        gemm_mma_kernel<<<dim3(QKV_N_ / 128, ROWS_ / 128), 256>>>(
            px, pqkvT + (size_t)l * QKV_N_ * C_, nullptr, pqkv, QKV_N_, 0);
        // attention
        attn_mma_kernel<<<dim3(N_ / 128, H_, B_), 256, ATTN_SMEM>>>(pqkv, pattn);
        // proj
        gemm_mma_kernel<<<dim3(C_ / 128, ROWS_ / 128), 256>>>(
            pattn, pprojT + (size_t)l * C_ * C_, proj_b + (size_t)l * C_, ptmp, C_, 1);
        // x = LN(x + proj_out)
        add_ln_kernel<<<ROWS_, C_>>>(px, ptmp, g1 + (size_t)l * C_, be1 + (size_t)l * C_, px);
        // h = gelu(x @ w1 + b1)
        gemm_mma_kernel<<<dim3(C_ / 128, ROWS_ / 128), 256>>>(
            px, pw1T + (size_t)l * C_ * C_, b1 + (size_t)l * C_, ph, C_, 2);
        // mlp = h @ w2 + b2
        gemm_mma_kernel<<<dim3(C_ / 128, ROWS_ / 128), 256>>>(
            ph, pw2T + (size_t)l * C_ * C_, b2 + (size_t)l * C_, ptmp, C_, 1);
        // x = LN(x + mlp); final layer -> d_out
        float* dst = (l == L_ - 1) ? out : px;
        add_ln_kernel<<<ROWS_, C_>>>(px, ptmp, g2 + (size_t)l * C_, be2 + (size_t)l * C_, dst);
    }
}

// round 4
// speedup vs baseline: 3.7397x; 1.5375x over previous
#include <cuda_runtime.h>
#include <math.h>
#include <stdint.h>

#define B_ 2
#define N_ 2048
#define C_ 256
#define L_ 4
#define H_ 8
#define DH_ 32
#define ROWS_ (B_ * N_)          // 4096
#define QKV_N_ (3 * C_)          // 768
#define LOG2E_ 1.4426950408889634f
#define QSCALE_ (0.17677669529663687f * LOG2E_)   // 1/sqrt(32) * log2(e)

// ===================== scratch (device globals; no allocs allowed) =====================
__device__ float g_x   [ROWS_ * C_];
__device__ float g_qkv [ROWS_ * QKV_N_];
__device__ float g_attn[ROWS_ * C_];
__device__ float g_tmp [ROWS_ * C_];
__device__ float g_h   [ROWS_ * C_];
// transposed weights: [N][K] K-major
__device__ float g_qkvT [L_ * QKV_N_ * C_];
__device__ float g_projT[L_ * C_ * C_];
__device__ float g_w1T  [L_ * C_ * C_];
__device__ float g_w2T  [L_ * C_ * C_];

// ===================== bf16 mma helpers (baseline PTX, sm_80+) =====================
// pack two floats into bf16x2 (lo in low half, hi in high half)
__device__ __forceinline__ uint32_t f2bf2(float lo, float hi) {
    uint32_t r;
    asm("cvt.rn.bf16x2.f32 %0, %1, %2;" : "=r"(r) : "f"(hi), "f"(lo));
    return r;
}

// D(16x8) += A(16x16) @ B(16x8), row.col, bf16 in / f32 accum
__device__ __forceinline__ void mma_bf16(float* d, const uint32_t* a, const uint32_t* b) {
    asm volatile(
        "mma.sync.aligned.m16n8k16.row.col.f32.bf16.bf16.f32 "
        "{%0,%1,%2,%3}, {%4,%5,%6,%7}, {%8,%9}, {%0,%1,%2,%3};"
        : "+f"(d[0]), "+f"(d[1]), "+f"(d[2]), "+f"(d[3])
        : "r"(a[0]), "r"(a[1]), "r"(a[2]), "r"(a[3]), "r"(b[0]), "r"(b[1]));
}

// ===================== weight transpose: out[n][k] = in[k][n], per layer (blockIdx.z) ====
__global__ __launch_bounds__(256) void transpose_kernel(
    const float* __restrict__ in, float* __restrict__ out, int K, int Nn)
{
    __shared__ float t[32][33];
    int z = blockIdx.z;
    const float* inl = in + (size_t)z * K * Nn;
    float* outl = out + (size_t)z * Nn * K;
    int tx = threadIdx.x, ty = threadIdx.y;
    int x = blockIdx.x * 32 + tx;     // n
    int y = blockIdx.y * 32 + ty;     // k
#pragma unroll
    for (int j = 0; j < 4; j++)
        t[ty + 8 * j][tx] = inl[(size_t)(y + 8 * j) * Nn + x];
    __syncthreads();
    int x2 = blockIdx.y * 32 + tx;    // k
    int y2 = blockIdx.x * 32 + ty;    // n
#pragma unroll
    for (int j = 0; j < 4; j++)
        outl[(size_t)(y2 + 8 * j) * K + x2] = t[tx][ty + 8 * j];
}

// ===================== positional embedding add =====================
__global__ void addpos_kernel(const float* __restrict__ x, float* __restrict__ out) {
    int n = blockIdx.x;
    int c = threadIdx.x;
    int j = c & ~1;
    float div = __expf((float)j * (-9.210340371976184f / 256.0f));
    float ang = (float)n * div;
    float pe = (c & 1) ? cosf(ang) : sinf(ang);
    size_t i0 = (size_t)n * C_ + c;
    size_t i1 = (size_t)(N_ + n) * C_ + c;
    out[i0] = x[i0] + pe;
    out[i1] = x[i1] + pe;
}

// ===================== bf16 mma GEMM: C = A(4096x256) @ BT(Nx256)^T ====================
// grid (Nn/128, 4096/128), 256 threads = 8 warps; warp tile 64x32; K = 256 fixed.
// k-chunk 16 per iteration (one m16n8k16 step), double-buffered.
// smem row = 8 uint32 (16 bf16) + 4 pad = stride 12 (conflict-free frag reads).
// mode: 0=none, 1=bias, 2=bias+gelu
#define GS 12

__global__ __launch_bounds__(256) void gemm_mma_kernel(
    const float* __restrict__ A, const float* __restrict__ BT,
    const float* __restrict__ bias, float* __restrict__ Cc,
    int Nn, int mode)
{
    __shared__ __align__(16) uint32_t sA[2][128 * GS];
    __shared__ __align__(16) uint32_t sB[2][128 * GS];

    const int tid = threadIdx.x, w = tid >> 5, lane = tid & 31;
    const int g = lane >> 2, tg = lane & 3;
    const int wm = (w & 1) * 64, wn = (w >> 1) * 32;
    const int brow = blockIdx.y * 128, bcol = blockIdx.x * 128;

    float acc[4][4][4];
#pragma unroll
    for (int mt = 0; mt < 4; mt++)
#pragma unroll
        for (int nt = 0; nt < 4; nt++)
#pragma unroll
            for (int i = 0; i < 4; i++) acc[mt][nt][i] = 0.f;

    const int srow = tid >> 1, shalf = (tid & 1) * 8;   // 8 floats per thread per matrix
    const float4* agp = (const float4*)(A + (size_t)(brow + srow) * 256 + shalf);
    const float4* bgp = (const float4*)(BT + (size_t)(bcol + srow) * 256 + shalf);

    float4 ra0 = agp[0], ra1 = agp[1];
    float4 rb0 = bgp[0], rb1 = bgp[1];

    const int sidx = srow * GS + (tid & 1) * 4;   // uint32 index (16B aligned)
#pragma unroll 1
    for (int it = 0; it < 16; it++) {
        const int cur = it & 1;
        {
            uint4 ua = make_uint4(f2bf2(ra0.x, ra0.y), f2bf2(ra0.z, ra0.w),
                                  f2bf2(ra1.x, ra1.y), f2bf2(ra1.z, ra1.w));
            *(uint4*)(&sA[cur][sidx]) = ua;
            uint4 ub = make_uint4(f2bf2(rb0.x, rb0.y), f2bf2(rb0.z, rb0.w),
                                  f2bf2(rb1.x, rb1.y), f2bf2(rb1.z, rb1.w));
            *(uint4*)(&sB[cur][sidx]) = ub;
        }
        __syncthreads();
        if (it < 15) {
            ra0 = agp[(it + 1) * 4];     ra1 = agp[(it + 1) * 4 + 1];
            rb0 = bgp[(it + 1) * 4];     rb1 = bgp[(it + 1) * 4 + 1];
        }
        // one k16 step
        uint32_t afr[4][4];
#pragma unroll
        for (int mt = 0; mt < 4; mt++) {
            int r = wm + mt * 16 + g;
            afr[mt][0] = sA[cur][(r    ) * GS + tg];
            afr[mt][1] = sA[cur][(r + 8) * GS + tg];
            afr[mt][2] = sA[cur][(r    ) * GS + tg + 4];
            afr[mt][3] = sA[cur][(r + 8) * GS + tg + 4];
        }
        uint32_t bfr[4][2];
#pragma unroll
        for (int nt = 0; nt < 4; nt++) {
            int n = wn + nt * 8 + g;
            bfr[nt][0] = sB[cur][n * GS + tg];
            bfr[nt][1] = sB[cur][n * GS + tg + 4];
        }
#pragma unroll
        for (int mt = 0; mt < 4; mt++)
#pragma unroll
            for (int nt = 0; nt < 4; nt++)
                mma_bf16(acc[mt][nt], afr[mt], bfr[nt]);
        __syncthreads();
    }

    // epilogue
#pragma unroll
    for (int mt = 0; mt < 4; mt++) {
        int r0 = brow + wm + mt * 16 + g;
#pragma unroll
        for (int nt = 0; nt < 4; nt++) {
            int cc = bcol + wn + nt * 8 + 2 * tg;
            float bi0 = 0.f, bi1 = 0.f;
            if (mode >= 1) { bi0 = bias[cc]; bi1 = bias[cc + 1]; }
            float v0 = acc[mt][nt][0] + bi0;
            float v1 = acc[mt][nt][1] + bi1;
            float v2 = acc[mt][nt][2] + bi0;
            float v3 = acc[mt][nt][3] + bi1;
            if (mode == 2) {
                v0 = 0.5f * v0 * (1.0f + erff(v0 * 0.70710678118654752f));
                v1 = 0.5f * v1 * (1.0f + erff(v1 * 0.70710678118654752f));
                v2 = 0.5f * v2 * (1.0f + erff(v2 * 0.70710678118654752f));
                v3 = 0.5f * v3 * (1.0f + erff(v3 * 0.70710678118654752f));
            }
            *(float2*)(Cc + (size_t)r0 * Nn + cc)       = make_float2(v0, v1);
            *(float2*)(Cc + (size_t)(r0 + 8) * Nn + cc) = make_float2(v2, v3);
        }
    }
}

// ===================== bf16 mma flash attention =====================
// grid (N/128, H, B), 256 threads = 8 warps; warp w owns q rows w*16..w*16+15.
// smem (uint32 units): sQ[128][20], sK[128][20], sVt[32][68] (V transposed: dh x key),
// sP[128][68]. Total 16000 u32 = 64000 B (dynamic).
#define QS20 20
#define PS68 68
#define SQ_OFF 0
#define SK_OFF (128 * QS20)
#define SV_OFF (2 * 128 * QS20)
#define SP_OFF (SV_OFF + 32 * PS68)
#define ATTN_SMEM ((SP_OFF + 128 * PS68) * 4)

__global__ __launch_bounds__(256) void attn_mma_kernel(
    const float* __restrict__ qkv, float* __restrict__ out)
{
    extern __shared__ __align__(16) uint32_t sm4[];
    uint32_t* sQ  = sm4 + SQ_OFF;
    uint32_t* sK  = sm4 + SK_OFF;
    uint32_t* sVt = sm4 + SV_OFF;
    uint32_t* sP  = sm4 + SP_OFF;

    const int tid = threadIdx.x, w = tid >> 5, lane = tid & 31;
    const int g = lane >> 2, tg = lane & 3;
    const int qt = blockIdx.x, h = blockIdx.y, b = blockIdx.z;

    const int srow = tid >> 1, shalf = tid & 1;   // staging: row + half (16 floats)

    // ---- stage Q (pre-scaled into exp2 domain, bf16) ----
    {
        const float4* qp = (const float4*)(qkv +
            ((size_t)(b * N_ + qt * 128 + srow) * QKV_N_) + h * DH_ + shalf * 16);
        uint32_t* dst = sQ + srow * QS20 + shalf * 8;
#pragma unroll
        for (int i = 0; i < 2; i++) {
            float4 v0 = qp[2 * i], v1 = qp[2 * i + 1];
            uint4 u = make_uint4(
                f2bf2(v0.x * QSCALE_, v0.y * QSCALE_),
                f2bf2(v0.z * QSCALE_, v0.w * QSCALE_),
                f2bf2(v1.x * QSCALE_, v1.y * QSCALE_),
                f2bf2(v1.z * QSCALE_, v1.w * QSCALE_));
            *(uint4*)(dst + 4 * i) = u;
        }
    }

    float oacc[4][4];
#pragma unroll
    for (int nt = 0; nt < 4; nt++)
#pragma unroll
        for (int i = 0; i < 4; i++) oacc[nt][i] = 0.f;
    float m0 = -1e30f, m1 = -1e30f, l0 = 0.f, l1 = 0.f;

    for (int kt = 0; kt < N_ / 128; kt++) {
        // ---- stage K (row-major bf16) ----
        {
            const float4* kp = (const float4*)(qkv +
                ((size_t)(b * N_ + kt * 128 + srow) * QKV_N_) + C_ + h * DH_ + shalf * 16);
            uint32_t* dst = sK + srow * QS20 + shalf * 8;
#pragma unroll
            for (int i = 0; i < 2; i++) {
                float4 v0 = kp[2 * i], v1 = kp[2 * i + 1];
                uint4 u = make_uint4(f2bf2(v0.x, v0.y), f2bf2(v0.z, v0.w),
                                     f2bf2(v1.x, v1.y), f2bf2(v1.z, v1.w));
                *(uint4*)(dst + 4 * i) = u;
            }
        }
        // ---- stage V transposed: sVt[dh][key-pair], lane-pair shfl over keys ----
        {
            const float4* vp = (const float4*)(qkv +
                ((size_t)(b * N_ + kt * 128 + srow) * QKV_N_) + 2 * C_ + h * DH_ + shalf * 16);
            float v[16];
#pragma unroll
            for (int i = 0; i < 4; i++) {
                float4 t4 = vp[i];
                v[4 * i] = t4.x; v[4 * i + 1] = t4.y; v[4 * i + 2] = t4.z; v[4 * i + 3] = t4.w;
            }
            uint32_t packed[16];
#pragma unroll
            for (int i = 0; i < 16; i++) {
                float o = __shfl_xor_sync(0xffffffffu, v[i], 2);   // key partner (key^1)
                packed[i] = (tid & 2) ? f2bf2(o, v[i]) : f2bf2(v[i], o);
            }
            int colp = tid >> 2;                 // key pair index
            int ib = (tid & 2) ? 8 : 0;          // split writes between pair threads
#pragma unroll
            for (int j = 0; j < 8; j++) {
                int i = ib + j;
                sVt[(shalf * 16 + i) * PS68 + colp] = packed[i];
            }
        }
        __syncthreads();

        // ---- S = Q @ K^T : warp tile 16 x 128, k = 32 (2 k16 steps) ----
        float sacc[16][4];
#pragma unroll
        for (int nt = 0; nt < 16; nt++)
#pragma unroll
            for (int i = 0; i < 4; i++) sacc[nt][i] = 0.f;

#pragma unroll
        for (int ks = 0; ks < 2; ks++) {
            uint32_t afr[4];
            afr[0] = sQ[(w * 16 + g    ) * QS20 + ks * 8 + tg];
            afr[1] = sQ[(w * 16 + g + 8) * QS20 + ks * 8 + tg];
            afr[2] = sQ[(w * 16 + g    ) * QS20 + ks * 8 + tg + 4];
            afr[3] = sQ[(w * 16 + g + 8) * QS20 + ks * 8 + tg + 4];
#pragma unroll
            for (int nt = 0; nt < 16; nt++) {
                uint32_t bfr[2];
                bfr[0] = sK[(nt * 8 + g) * QS20 + ks * 8 + tg];
                bfr[1] = sK[(nt * 8 + g) * QS20 + ks * 8 + tg + 4];
                mma_bf16(sacc[nt], afr, bfr);
            }
        }

        // ---- online softmax (rows r0 = w*16+g, r1 = r0+8), exp2 domain ----
        float nm0 = -1e30f, nm1 = -1e30f;
#pragma unroll
        for (int nt = 0; nt < 16; nt++) {
            nm0 = fmaxf(nm0, fmaxf(sacc[nt][0], sacc[nt][1]));
            nm1 = fmaxf(nm1, fmaxf(sacc[nt][2], sacc[nt][3]));
        }
        nm0 = fmaxf(nm0, __shfl_xor_sync(0xffffffffu, nm0, 1));
        nm0 = fmaxf(nm0, __shfl_xor_sync(0xffffffffu, nm0, 2));
        nm1 = fmaxf(nm1, __shfl_xor_sync(0xffffffffu, nm1, 1));
        nm1 = fmaxf(nm1, __shfl_xor_sync(0xffffffffu, nm1, 2));
        nm0 = fmaxf(nm0, m0);
        nm1 = fmaxf(nm1, m1);
        float f0 = exp2f(m0 - nm0), f1 = exp2f(m1 - nm1);
        m0 = nm0; m1 = nm1;

        float ps0 = 0.f, ps1 = 0.f;
        uint32_t* sPr0 = sP + (w * 16 + g    ) * PS68 + tg;
        uint32_t* sPr1 = sP + (w * 16 + g + 8) * PS68 + tg;
#pragma unroll
        for (int nt = 0; nt < 16; nt++) {
            float p00 = exp2f(sacc[nt][0] - m0);
            float p01 = exp2f(sacc[nt][1] - m0);
            float p10 = exp2f(sacc[nt][2] - m1);
            float p11 = exp2f(sacc[nt][3] - m1);
            ps0 += p00 + p01;
            ps1 += p10 + p11;
            sPr0[nt * 4] = f2bf2(p00, p01);
            sPr1[nt * 4] = f2bf2(p10, p11);
        }
        ps0 += __shfl_xor_sync(0xffffffffu, ps0, 1);
        ps0 += __shfl_xor_sync(0xffffffffu, ps0, 2);
        ps1 += __shfl_xor_sync(0xffffffffu, ps1, 1);
        ps1 += __shfl_xor_sync(0xffffffffu, ps1, 2);
        l0 = l0 * f0 + ps0;
        l1 = l1 * f1 + ps1;

#pragma unroll
        for (int nt = 0; nt < 4; nt++) {
            oacc[nt][0] *= f0; oacc[nt][1] *= f0;
            oacc[nt][2] *= f1; oacc[nt][3] *= f1;
        }
        __syncwarp();

        // ---- O += P @ V : warp tile 16 x 32, k = 128 (8 k16 steps) ----
#pragma unroll
        for (int ks = 0; ks < 8; ks++) {
            uint32_t afr[4];
            afr[0] = sP[(w * 16 + g    ) * PS68 + ks * 8 + tg];
            afr[1] = sP[(w * 16 + g + 8) * PS68 + ks * 8 + tg];
            afr[2] = sP[(w * 16 + g    ) * PS68 + ks * 8 + tg + 4];
            afr[3] = sP[(w * 16 + g + 8) * PS68 + ks * 8 + tg + 4];
#pragma unroll
            for (int nt = 0; nt < 4; nt++) {
                uint32_t bfr[2];
                bfr[0] = sVt[(nt * 8 + g) * PS68 + ks * 8 + tg];
                bfr[1] = sVt[(nt * 8 + g) * PS68 + ks * 8 + tg + 4];
                mma_bf16(oacc[nt], afr, bfr);
            }
        }
        __syncthreads();
    }

    // ---- epilogue ----
    float inv0 = 1.0f / l0, inv1 = 1.0f / l1;
    int q0 = qt * 128 + w * 16 + g;
    float* op0 = out + ((size_t)(b * N_ + q0)) * C_ + h * DH_;
    float* op1 = op0 + (size_t)8 * C_;
#pragma unroll
    for (int nt = 0; nt < 4; nt++) {
        int cc = nt * 8 + 2 * tg;
        *(float2*)(op0 + cc) = make_float2(oacc[nt][0] * inv0, oacc[nt][1] * inv0);
        *(float2*)(op1 + cc) = make_float2(oacc[nt][2] * inv1, oacc[nt][3] * inv1);
    }
}

// ===================== fused residual add + layernorm =====================
__global__ __launch_bounds__(256) void add_ln_kernel(
    const float* __restrict__ x, const float* __restrict__ y,
    const float* __restrict__ g, const float* __restrict__ be,
    float* __restrict__ out)
{
    int row = blockIdx.x;
    int c = threadIdx.x;
    float v = x[(size_t)row * C_ + c] + y[(size_t)row * C_ + c];

    __shared__ float red[8];
    float s = v;
#pragma unroll
    for (int o = 16; o > 0; o >>= 1) s += __shfl_down_sync(0xffffffffu, s, o);
    if ((c & 31) == 0) red[c >> 5] = s;
    __syncthreads();
    float mu = 0.f;
#pragma unroll
    for (int i = 0; i < 8; i++) mu += red[i];
    mu *= (1.0f / C_);
    __syncthreads();
    float dv = v - mu;
    float s2 = dv * dv;
#pragma unroll
    for (int o = 16; o > 0; o >>= 1) s2 += __shfl_down_sync(0xffffffffu, s2, o);
    if ((c & 31) == 0) red[c >> 5] = s2;
    __syncthreads();
    float var = 0.f;
#pragma unroll
    for (int i = 0; i < 8; i++) var += red[i];
    var *= (1.0f / C_);

    out[(size_t)row * C_ + c] = dv * rsqrtf(var + 1e-6f) * g[c] + be[c];
}

// ===================== launch =====================
extern "C" void kernel_launch(void* const* d_in, const int* in_sizes, int n_in,
                              void* d_out, int out_size)
{
    const float* x_in   = (const float*)d_in[0];
    const float* qkv_w  = (const float*)d_in[1];
    const float* proj_w = (const float*)d_in[2];
    const float* proj_b = (const float*)d_in[3];
    const float* w1     = (const float*)d_in[4];
    const float* b1     = (const float*)d_in[5];
    const float* w2     = (const float*)d_in[6];
    const float* b2     = (const float*)d_in[7];
    const float* g1     = (const float*)d_in[8];
    const float* be1    = (const float*)d_in[9];
    const float* g2     = (const float*)d_in[10];
    const float* be2    = (const float*)d_in[11];
    float* out = (float*)d_out;

    float *px, *pqkv, *pattn, *ptmp, *ph;
    float *pqkvT, *pprojT, *pw1T, *pw2T;
    cudaGetSymbolAddress((void**)&px,    g_x);
    cudaGetSymbolAddress((void**)&pqkv,  g_qkv);
    cudaGetSymbolAddress((void**)&pattn, g_attn);
    cudaGetSymbolAddress((void**)&ptmp,  g_tmp);
    cudaGetSymbolAddress((void**)&ph,    g_h);
    cudaGetSymbolAddress((void**)&pqkvT, g_qkvT);
    cudaGetSymbolAddress((void**)&pprojT,g_projT);
    cudaGetSymbolAddress((void**)&pw1T,  g_w1T);
    cudaGetSymbolAddress((void**)&pw2T,  g_w2T);

    static bool attr_done = false;
    if (!attr_done) {
        cudaFuncSetAttribute(attn_mma_kernel,
                             cudaFuncAttributeMaxDynamicSharedMemorySize, ATTN_SMEM);
        attr_done = true;
    }

    // transpose weights to [N][K] K-major
    transpose_kernel<<<dim3(QKV_N_ / 32, C_ / 32, L_), dim3(32, 8)>>>(qkv_w, pqkvT, C_, QKV_N_);
    transpose_kernel<<<dim3(C_ / 32, C_ / 32, L_),     dim3(32, 8)>>>(proj_w, pprojT, C_, C_);
    transpose_kernel<<<dim3(C_ / 32, C_ / 32, L_),     dim3(32, 8)>>>(w1, pw1T, C_, C_);
    transpose_kernel<<<dim3(C_ / 32, C_ / 32, L_),     dim3(32, 8)>>>(w2, pw2T, C_, C_);

    addpos_kernel<<<N_, C_>>>(x_in, px);

    for (int l = 0; l < L_; l++) {
        // qkv = x @ qkv_w[l]
        gemm_mma_kernel<<<dim3(QKV_N_ / 128, ROWS_ / 128), 256>>>(
            px, pqkvT + (size_t)l * QKV_N_ * C_, nullptr, pqkv, QKV_N_, 0);
        // attention
        attn_mma_kernel<<<dim3(N_ / 128, H_, B_), 256, ATTN_SMEM>>>(pqkv, pattn);
        // proj
        gemm_mma_kernel<<<dim3(C_ / 128, ROWS_ / 128), 256>>>(
            pattn, pprojT + (size_t)l * C_ * C_, proj_b + (size_t)l * C_, ptmp, C_, 1);
        // x = LN(x + proj_out)
        add_ln_kernel<<<ROWS_, C_>>>(px, ptmp, g1 + (size_t)l * C_, be1 + (size_t)l * C_, px);
        // h = gelu(x @ w1 + b1)
        gemm_mma_kernel<<<dim3(C_ / 128, ROWS_ / 128), 256>>>(
            px, pw1T + (size_t)l * C_ * C_, b1 + (size_t)l * C_, ph, C_, 2);
        // mlp = h @ w2 + b2
        gemm_mma_kernel<<<dim3(C_ / 128, ROWS_ / 128), 256>>>(
            ph, pw2T + (size_t)l * C_ * C_, b2 + (size_t)l * C_, ptmp, C_, 1);
        // x = LN(x + mlp); final layer -> d_out
        float* dst = (l == L_ - 1) ? out : px;
        add_ln_kernel<<<ROWS_, C_>>>(px, ptmp, g2 + (size_t)l * C_, be2 + (size_t)l * C_, dst);
    }
}